// round 16
// baseline (speedup 1.0000x reference)
#include <cuda_runtime.h>

#define HH 512
#define WW 512
#define NIMG 12
#define RAD 3
#define TX 64
#define TY 16
#define TILE_H 22            // TY + 2*RAD
#define SV_H   19            // TY + RAD
#define PITCH  76            // padded shared pitch (float4-aligned)
// halo storage offset = 4: output pixel x <-> smem col x+4; window cols x+1..x+7.

typedef unsigned long long u64;

// ping-pong scratch (allocation-free: static device globals)
__device__ float g_imA[NIMG*HH*WW];
__device__ float g_ptA[NIMG*HH*WW];
__device__ float g_imB[NIMG*HH*WW];
__device__ float g_ptB[NIMG*HH*WW];

__device__ __forceinline__ u64 ADD2(u64 a, u64 b) {
    u64 c; asm("add.rn.f32x2 %0, %1, %2;" : "=l"(c) : "l"(a), "l"(b)); return c;
}

__global__ __launch_bounds__(128, 8)
void swf_step(const float* __restrict__ im_in, const float* __restrict__ pt_in,
              float* __restrict__ im_out, float* __restrict__ pt_out,
              int write_im)
{
    __shared__ float s [2][TILE_H][PITCH];   // 13.4 KB
    __shared__ float sv[2][SV_H][PITCH];     // 11.6 KB  -> 24.9 KB total, 8 blocks/SM

    const int img = blockIdx.z;
    const int x0 = blockIdx.x * TX;
    const int y0 = blockIdx.y * TY;
    const float* __restrict__ imI = im_in + (size_t)img * HH * WW;
    const float* __restrict__ ptI = pt_in + (size_t)img * HH * WW;

    const int tid = threadIdx.x;

    // ---- stage 1a: main region via LDG.128 -> aligned STS.128 (y-check only) ----
    {
        const int PER_A = TILE_H * 16;             // 352 f4-groups per array
        for (int r = tid; r < 2 * PER_A; r += 128) {
            int a  = r >= PER_A;
            int rr = r - (a ? PER_A : 0);
            int ly = rr >> 4, lx4 = (rr & 15) << 2;
            int gy = y0 - RAD + ly;
            const float* src = a ? ptI : imI;
            float4 val = make_float4(0.f, 0.f, 0.f, 0.f);
            if (gy >= 0 && gy < HH)
                val = *(const float4*)(src + gy * WW + x0 + lx4);
            *(float4*)&s[a][ly][lx4 + 4] = val;    // 16B-aligned
        }
    }
    // ---- stage 1b: 6 halo columns (cols 1,2,3 and 68,69,70), scalar, full bounds ----
    {
        const int PER_A = TILE_H * 6;
        for (int r = tid; r < 2 * PER_A; r += 128) {
            int a  = r >= PER_A;
            int rr = r - (a ? PER_A : 0);
            int ly = rr / 6;
            int hx = rr - 6 * ly;
            int lx = (hx < 3) ? hx + 1 : hx + 65;  // 1,2,3 / 68,69,70
            int gy = y0 - RAD + ly, gx = x0 - 4 + lx;
            float val = 0.f;
            if (gy >= 0 && gy < HH && gx >= 0 && gx < WW)
                val = (a ? ptI : imI)[gy * WW + gx];
            s[a][ly][lx] = val;
        }
    }
    __syncthreads();

    // ---- stage 2: vertical 4-row sums with packed f32x2 (lane-independent, safe) ----
    #pragma unroll
    for (int a = 0; a < 2; a++) {
        for (int r = tid; r < SV_H * 16; r += 128) {
            int j = r >> 4, lx = (r & 15) << 2;
            ulonglong2 r0 = *(const ulonglong2*)&s[a][j    ][lx];
            ulonglong2 r1 = *(const ulonglong2*)&s[a][j + 1][lx];
            ulonglong2 r2 = *(const ulonglong2*)&s[a][j + 2][lx];
            ulonglong2 r3 = *(const ulonglong2*)&s[a][j + 3][lx];
            ulonglong2 o;
            o.x = ADD2(ADD2(r0.x, r1.x), ADD2(r2.x, r3.x));
            o.y = ADD2(ADD2(r0.y, r1.y), ADD2(r2.y, r3.y));
            *(ulonglong2*)&sv[a][j][lx] = o;
        }
        for (int r = tid; r < SV_H * 2; r += 128) {
            int j = r >> 1, lx = 64 + ((r & 1) << 2);
            ulonglong2 r0 = *(const ulonglong2*)&s[a][j    ][lx];
            ulonglong2 r1 = *(const ulonglong2*)&s[a][j + 1][lx];
            ulonglong2 r2 = *(const ulonglong2*)&s[a][j + 2][lx];
            ulonglong2 r3 = *(const ulonglong2*)&s[a][j + 3][lx];
            ulonglong2 o;
            o.x = ADD2(ADD2(r0.x, r1.x), ADD2(r2.x, r3.x));
            o.y = ADD2(ADD2(r0.y, r1.y), ADD2(r2.y, r3.y));
            *(ulonglong2*)&sv[a][j][lx] = o;
        }
    }
    __syncthreads();

    // ---- stage 3: 8 px per thread, 2 independent 4-px chunks 32 cols apart ----
    const int oy  = tid >> 3;                 // 0..15
    const int xb  = (tid & 7) << 2;           // 0,4,...,28
    const float inv16 = 1.f / 16.f;
    const float inv28 = 1.f / 28.f;

    float u[12], v[12], c[12];
    float qu[7], qv[7], hc[7];

    #define LOAD3(A, XS)                                                     \
        {                                                                    \
            float4 t0, t1, t2;                                               \
            t0 = *(const float4*)&sv[A][oy][(XS)];                           \
            t1 = *(const float4*)&sv[A][oy][(XS) + 4];                       \
            t2 = *(const float4*)&sv[A][oy][(XS) + 8];                       \
            u[0]=t0.x; u[1]=t0.y; u[2]=t0.z; u[3]=t0.w;                      \
            u[4]=t1.x; u[5]=t1.y; u[6]=t1.z; u[7]=t1.w;                      \
            u[8]=t2.x; u[9]=t2.y; u[10]=t2.z; u[11]=t2.w;                    \
            t0 = *(const float4*)&sv[A][oy + 3][(XS)];                       \
            t1 = *(const float4*)&sv[A][oy + 3][(XS) + 4];                   \
            t2 = *(const float4*)&sv[A][oy + 3][(XS) + 8];                   \
            v[0]=t0.x; v[1]=t0.y; v[2]=t0.z; v[3]=t0.w;                      \
            v[4]=t1.x; v[5]=t1.y; v[6]=t1.z; v[7]=t1.w;                      \
            v[8]=t2.x; v[9]=t2.y; v[10]=t2.z; v[11]=t2.w;                    \
            t0 = *(const float4*)&s[A][oy + 3][(XS)];                        \
            t1 = *(const float4*)&s[A][oy + 3][(XS) + 4];                    \
            t2 = *(const float4*)&s[A][oy + 3][(XS) + 8];                    \
            c[0]=t0.x; c[1]=t0.y; c[2]=t0.z; c[3]=t0.w;                      \
            c[4]=t1.x; c[5]=t1.y; c[6]=t1.z; c[7]=t1.w;                      \
            c[8]=t2.x; c[9]=t2.y; c[10]=t2.z; c[11]=t2.w;                    \
        }

    // sums over window indices 1..10 (element 0 and 11 are outside the window)
    #define QSUMS()                                                         \
        {                                                                    \
            float pu[9], pv[9], pc[9];                                       \
            _Pragma("unroll")                                                \
            for (int i = 0; i < 9; i++) {                                    \
                pu[i] = u[i+1] + u[i+2];                                     \
                pv[i] = v[i+1] + v[i+2];                                     \
                pc[i] = c[i+1] + c[i+2];                                     \
            }                                                                \
            _Pragma("unroll")                                                \
            for (int i = 0; i < 7; i++) {                                    \
                qu[i] = pu[i] + pu[i+2];                                     \
                qv[i] = pv[i] + pv[i+2];                                     \
                hc[i] = pc[i] + pc[i+2];                                     \
            }                                                                \
        }

    const int grow = img * HH * WW + (y0 + oy) * WW + x0;
    unsigned pack[2];

    // ===== pass A: im -> packed argmin indices + filtered im =====
    #pragma unroll
    for (int ch = 0; ch < 2; ch++) {
        const int xs = xb + (ch << 5);
        LOAD3(0, xs)
        QSUMS()
        float bi[4];
        unsigned pk = 0;
        #pragma unroll
        for (int p = 0; p < 4; p++) {
            float qnw = qu[p], qne = qu[p+3], qsw = qv[p], qse = qv[p+3];
            float z = c[p+4];
            float dd[8];
            dd[0] = ((qnw + qsw) - hc[p  ]) * inv28;   // L
            dd[1] = ((qne + qse) - hc[p+3]) * inv28;   // R
            dd[2] = ((qnw + qne) - u[p+4]) * inv28;    // U
            dd[3] = ((qsw + qse) - v[p+4]) * inv28;    // D
            dd[4] = qnw * inv16;                       // NW
            dd[5] = qne * inv16;                       // NE
            dd[6] = qsw * inv16;                       // SW
            dd[7] = qse * inv16;                       // SE
            // tournament argmin, left wins ties == first minimum
            float aa[8];
            #pragma unroll
            for (int k = 0; k < 8; k++) aa[k] = fabsf(dd[k] - z);
            float a01 = aa[1] < aa[0] ? aa[1] : aa[0];  float v01 = aa[1] < aa[0] ? dd[1] : dd[0];  int i01 = aa[1] < aa[0] ? 1 : 0;
            float a23 = aa[3] < aa[2] ? aa[3] : aa[2];  float v23 = aa[3] < aa[2] ? dd[3] : dd[2];  int i23 = aa[3] < aa[2] ? 3 : 2;
            float a45 = aa[5] < aa[4] ? aa[5] : aa[4];  float v45 = aa[5] < aa[4] ? dd[5] : dd[4];  int i45 = aa[5] < aa[4] ? 5 : 4;
            float a67 = aa[7] < aa[6] ? aa[7] : aa[6];  float v67 = aa[7] < aa[6] ? dd[7] : dd[6];  int i67 = aa[7] < aa[6] ? 7 : 6;
            float a03 = a23 < a01 ? a23 : a01;  float v03 = a23 < a01 ? v23 : v01;  int i03 = a23 < a01 ? i23 : i01;
            float a47 = a67 < a45 ? a67 : a45;  float v47 = a67 < a45 ? v67 : v45;  int i47 = a67 < a45 ? i67 : i45;
            float bv = a47 < a03 ? v47 : v03;
            int   bk = a47 < a03 ? i47 : i03;
            bi[p] = bv;
            pk |= (unsigned)bk << (3 * p);
        }
        pack[ch] = pk;
        if (write_im)
            *(float4*)&im_out[grow + xs] = make_float4(bi[0], bi[1], bi[2], bi[3]);
    }

    // ===== pass B: pert, select by stored index =====
    #pragma unroll
    for (int ch = 0; ch < 2; ch++) {
        const int xs = xb + (ch << 5);
        LOAD3(1, xs)
        QSUMS()
        float bp[4];
        unsigned pk = pack[ch];
        #pragma unroll
        for (int p = 0; p < 4; p++) {
            float qnw = qu[p], qne = qu[p+3], qsw = qv[p], qse = qv[p+3];
            float d0 = ((qnw + qsw) - hc[p  ]) * inv28;
            float d1 = ((qne + qse) - hc[p+3]) * inv28;
            float d2 = ((qnw + qne) - u[p+4]) * inv28;
            float d3 = ((qsw + qse) - v[p+4]) * inv28;
            float d4 = qnw * inv16;
            float d5 = qne * inv16;
            float d6 = qsw * inv16;
            float d7 = qse * inv16;
            int bk = (pk >> (3 * p)) & 7;
            float e0 = (bk & 1) ? d1 : d0;
            float e1 = (bk & 1) ? d3 : d2;
            float e2 = (bk & 1) ? d5 : d4;
            float e3 = (bk & 1) ? d7 : d6;
            float f0 = (bk & 2) ? e1 : e0;
            float f1 = (bk & 2) ? e3 : e2;
            bp[p] = (bk & 4) ? f1 : f0;
        }
        *(float4*)&pt_out[grow + xs] = make_float4(bp[0], bp[1], bp[2], bp[3]);
    }
}

extern "C" void kernel_launch(void* const* d_in, const int* in_sizes, int n_in,
                              void* d_out, int out_size)
{
    const float* im = (const float*)d_in[0];
    const float* pt = (const float*)d_in[1];
    float* out = (float*)d_out;

    float *imA, *ptA, *imB, *ptB;
    cudaGetSymbolAddress((void**)&imA, g_imA);
    cudaGetSymbolAddress((void**)&ptA, g_ptA);
    cudaGetSymbolAddress((void**)&imB, g_imB);
    cudaGetSymbolAddress((void**)&ptB, g_ptB);

    dim3 grid(WW / TX, HH / TY, NIMG);   // (8,32,12) = 3072 blocks
    dim3 block(128);

    swf_step<<<grid, block>>>(im,  pt,  imA, ptA, 1);
    swf_step<<<grid, block>>>(imA, ptA, imB, ptB, 1);
    swf_step<<<grid, block>>>(imB, ptB, imA, ptA, 1);
    swf_step<<<grid, block>>>(imA, ptA, imB, ptB, 1);
    swf_step<<<grid, block>>>(imB, ptB, imA, ptA, 1);
    swf_step<<<grid, block>>>(imA, ptA, imB, out, 0);
}

// round 17
// speedup vs baseline: 1.0269x; 1.0269x over previous
#include <cuda_runtime.h>

#define HH 512
#define WW 512
#define NIMG 12
#define RAD 3
#define TX 64
#define TY 32
#define TILE_H 38            // TY + 2*RAD
#define SV_H   35            // TY + RAD
#define PITCH  76            // padded shared pitch (float4-aligned)
// halo storage offset = 4: output pixel x <-> smem col x+4; window cols x+1..x+7.

typedef unsigned long long u64;

// ping-pong scratch (allocation-free: static device globals)
__device__ float g_imA[NIMG*HH*WW];
__device__ float g_ptA[NIMG*HH*WW];
__device__ float g_imB[NIMG*HH*WW];
__device__ float g_ptB[NIMG*HH*WW];

__device__ __forceinline__ u64 ADD2(u64 a, u64 b) {
    u64 c; asm("add.rn.f32x2 %0, %1, %2;" : "=l"(c) : "l"(a), "l"(b)); return c;
}

__global__ __launch_bounds__(256, 4)
void swf_step(const float* __restrict__ im_in, const float* __restrict__ pt_in,
              float* __restrict__ im_out, float* __restrict__ pt_out,
              int write_im)
{
    __shared__ float s [2][TILE_H][PITCH];
    __shared__ float sv[2][SV_H][PITCH];

    const int img = blockIdx.z;
    const int x0 = blockIdx.x * TX;
    const int y0 = blockIdx.y * TY;
    const float* __restrict__ imI = im_in + (size_t)img * HH * WW;
    const float* __restrict__ ptI = pt_in + (size_t)img * HH * WW;

    const int tid = threadIdx.x;

    // ---- stage 1a: main region via LDG.128 -> aligned STS.128 (y-check only) ----
    {
        const int PER_A = TILE_H * 16;             // 608 f4-groups per array
        for (int r = tid; r < 2 * PER_A; r += 256) {
            int a  = r >= PER_A;
            int rr = r - (a ? PER_A : 0);
            int ly = rr >> 4, lx4 = (rr & 15) << 2;
            int gy = y0 - RAD + ly;
            const float* src = a ? ptI : imI;
            float4 val = make_float4(0.f, 0.f, 0.f, 0.f);
            if (gy >= 0 && gy < HH)
                val = *(const float4*)(src + gy * WW + x0 + lx4);
            *(float4*)&s[a][ly][lx4 + 4] = val;    // 16B-aligned
        }
    }
    // ---- stage 1b: 6 halo columns (cols 1,2,3 and 68,69,70), scalar, full bounds ----
    {
        const int PER_A = TILE_H * 6;
        for (int r = tid; r < 2 * PER_A; r += 256) {
            int a  = r >= PER_A;
            int rr = r - (a ? PER_A : 0);
            int ly = rr / 6;
            int hx = rr - 6 * ly;
            int lx = (hx < 3) ? hx + 1 : hx + 65;  // 1,2,3 / 68,69,70
            int gy = y0 - RAD + ly, gx = x0 - 4 + lx;
            float val = 0.f;
            if (gy >= 0 && gy < HH && gx >= 0 && gx < WW)
                val = (a ? ptI : imI)[gy * WW + gx];
            s[a][ly][lx] = val;
        }
    }
    __syncthreads();

    // ---- stage 2: vertical 4-row sums with packed f32x2 (lane-independent, safe) ----
    #pragma unroll
    for (int a = 0; a < 2; a++) {
        for (int r = tid; r < SV_H * 16; r += 256) {
            int j = r >> 4, lx = (r & 15) << 2;
            ulonglong2 r0 = *(const ulonglong2*)&s[a][j    ][lx];
            ulonglong2 r1 = *(const ulonglong2*)&s[a][j + 1][lx];
            ulonglong2 r2 = *(const ulonglong2*)&s[a][j + 2][lx];
            ulonglong2 r3 = *(const ulonglong2*)&s[a][j + 3][lx];
            ulonglong2 o;
            o.x = ADD2(ADD2(r0.x, r1.x), ADD2(r2.x, r3.x));
            o.y = ADD2(ADD2(r0.y, r1.y), ADD2(r2.y, r3.y));
            *(ulonglong2*)&sv[a][j][lx] = o;
        }
        for (int r = tid; r < SV_H * 2; r += 256) {
            int j = r >> 1, lx = 64 + ((r & 1) << 2);
            ulonglong2 r0 = *(const ulonglong2*)&s[a][j    ][lx];
            ulonglong2 r1 = *(const ulonglong2*)&s[a][j + 1][lx];
            ulonglong2 r2 = *(const ulonglong2*)&s[a][j + 2][lx];
            ulonglong2 r3 = *(const ulonglong2*)&s[a][j + 3][lx];
            ulonglong2 o;
            o.x = ADD2(ADD2(r0.x, r1.x), ADD2(r2.x, r3.x));
            o.y = ADD2(ADD2(r0.y, r1.y), ADD2(r2.y, r3.y));
            *(ulonglong2*)&sv[a][j][lx] = o;
        }
    }
    __syncthreads();

    // ---- stage 3: 8 px per thread, 2 independent 4-px chunks 32 cols apart ----
    const int oy  = tid >> 3;                 // 0..31
    const int xb  = (tid & 7) << 2;           // 0,4,...,28
    const float inv16 = 1.f / 16.f;
    const float inv28 = 1.f / 28.f;

    float u[12], v[12], c[12];
    float qu[7], qv[7], hc[7];

    #define LOAD3(A, XS)                                                     \
        {                                                                    \
            float4 t0, t1, t2;                                               \
            t0 = *(const float4*)&sv[A][oy][(XS)];                           \
            t1 = *(const float4*)&sv[A][oy][(XS) + 4];                       \
            t2 = *(const float4*)&sv[A][oy][(XS) + 8];                       \
            u[0]=t0.x; u[1]=t0.y; u[2]=t0.z; u[3]=t0.w;                      \
            u[4]=t1.x; u[5]=t1.y; u[6]=t1.z; u[7]=t1.w;                      \
            u[8]=t2.x; u[9]=t2.y; u[10]=t2.z; u[11]=t2.w;                    \
            t0 = *(const float4*)&sv[A][oy + 3][(XS)];                       \
            t1 = *(const float4*)&sv[A][oy + 3][(XS) + 4];                   \
            t2 = *(const float4*)&sv[A][oy + 3][(XS) + 8];                   \
            v[0]=t0.x; v[1]=t0.y; v[2]=t0.z; v[3]=t0.w;                      \
            v[4]=t1.x; v[5]=t1.y; v[6]=t1.z; v[7]=t1.w;                      \
            v[8]=t2.x; v[9]=t2.y; v[10]=t2.z; v[11]=t2.w;                    \
            t0 = *(const float4*)&s[A][oy + 3][(XS)];                        \
            t1 = *(const float4*)&s[A][oy + 3][(XS) + 4];                    \
            t2 = *(const float4*)&s[A][oy + 3][(XS) + 8];                    \
            c[0]=t0.x; c[1]=t0.y; c[2]=t0.z; c[3]=t0.w;                      \
            c[4]=t1.x; c[5]=t1.y; c[6]=t1.z; c[7]=t1.w;                      \
            c[8]=t2.x; c[9]=t2.y; c[10]=t2.z; c[11]=t2.w;                    \
        }

    // sums over window indices 1..10 (element 0 and 11 are outside the window)
    #define QSUMS()                                                         \
        {                                                                    \
            float pu[9], pv[9], pc[9];                                       \
            _Pragma("unroll")                                                \
            for (int i = 0; i < 9; i++) {                                    \
                pu[i] = u[i+1] + u[i+2];                                     \
                pv[i] = v[i+1] + v[i+2];                                     \
                pc[i] = c[i+1] + c[i+2];                                     \
            }                                                                \
            _Pragma("unroll")                                                \
            for (int i = 0; i < 7; i++) {                                    \
                qu[i] = pu[i] + pu[i+2];                                     \
                qv[i] = pv[i] + pv[i+2];                                     \
                hc[i] = pc[i] + pc[i+2];                                     \
            }                                                                \
        }

    const int grow = img * HH * WW + (y0 + oy) * WW + x0;
    unsigned pack[2];

    // ===== pass A: im -> packed argmin indices + filtered im =====
    #pragma unroll
    for (int ch = 0; ch < 2; ch++) {
        const int xs = xb + (ch << 5);
        LOAD3(0, xs)
        QSUMS()
        float bi[4];
        unsigned pk = 0;
        #pragma unroll
        for (int p = 0; p < 4; p++) {
            float qnw = qu[p], qne = qu[p+3], qsw = qv[p], qse = qv[p+3];
            float z = c[p+4];
            float dd[8];
            dd[0] = ((qnw + qsw) - hc[p  ]) * inv28;   // L
            dd[1] = ((qne + qse) - hc[p+3]) * inv28;   // R
            dd[2] = ((qnw + qne) - u[p+4]) * inv28;    // U
            dd[3] = ((qsw + qse) - v[p+4]) * inv28;    // D
            dd[4] = qnw * inv16;                       // NW
            dd[5] = qne * inv16;                       // NE
            dd[6] = qsw * inv16;                       // SW
            dd[7] = qse * inv16;                       // SE
            // tournament argmin, left wins ties == first minimum
            float aa[8];
            #pragma unroll
            for (int k = 0; k < 8; k++) aa[k] = fabsf(dd[k] - z);
            float a01 = aa[1] < aa[0] ? aa[1] : aa[0];  float v01 = aa[1] < aa[0] ? dd[1] : dd[0];  int i01 = aa[1] < aa[0] ? 1 : 0;
            float a23 = aa[3] < aa[2] ? aa[3] : aa[2];  float v23 = aa[3] < aa[2] ? dd[3] : dd[2];  int i23 = aa[3] < aa[2] ? 3 : 2;
            float a45 = aa[5] < aa[4] ? aa[5] : aa[4];  float v45 = aa[5] < aa[4] ? dd[5] : dd[4];  int i45 = aa[5] < aa[4] ? 5 : 4;
            float a67 = aa[7] < aa[6] ? aa[7] : aa[6];  float v67 = aa[7] < aa[6] ? dd[7] : dd[6];  int i67 = aa[7] < aa[6] ? 7 : 6;
            float a03 = a23 < a01 ? a23 : a01;  float v03 = a23 < a01 ? v23 : v01;  int i03 = a23 < a01 ? i23 : i01;
            float a47 = a67 < a45 ? a67 : a45;  float v47 = a67 < a45 ? v67 : v45;  int i47 = a67 < a45 ? i67 : i45;
            float bv = a47 < a03 ? v47 : v03;
            int   bk = a47 < a03 ? i47 : i03;
            bi[p] = bv;
            pk |= (unsigned)bk << (3 * p);
        }
        pack[ch] = pk;
        if (write_im)
            *(float4*)&im_out[grow + xs] = make_float4(bi[0], bi[1], bi[2], bi[3]);
    }

    // ===== pass B: pert -- select NUMERATOR by index, one final scale ====
    // bk 0..3 (half windows): numerator (q+q)-mid, scale 1/28.
    // bk 4..7 (quarters):     numerator q itself,  scale 1/16.
    // Scale applied after select to the same value => bit-identical to scaled-select.
    #pragma unroll
    for (int ch = 0; ch < 2; ch++) {
        const int xs = xb + (ch << 5);
        LOAD3(1, xs)
        QSUMS()
        float bp[4];
        unsigned pk = pack[ch];
        #pragma unroll
        for (int p = 0; p < 4; p++) {
            float qnw = qu[p], qne = qu[p+3], qsw = qv[p], qse = qv[p+3];
            float n0 = (qnw + qsw) - hc[p  ];   // L
            float n1 = (qne + qse) - hc[p+3];   // R
            float n2 = (qnw + qne) - u[p+4];    // U
            float n3 = (qsw + qse) - v[p+4];    // D
            int bk = (pk >> (3 * p)) & 7;
            float e0 = (bk & 1) ? n1  : n0;
            float e1 = (bk & 1) ? n3  : n2;
            float e2 = (bk & 1) ? qne : qnw;
            float e3 = (bk & 1) ? qse : qsw;
            float f0 = (bk & 2) ? e1 : e0;
            float f1 = (bk & 2) ? e3 : e2;
            float num = (bk & 4) ? f1 : f0;
            float sc  = (bk & 4) ? inv16 : inv28;
            bp[p] = num * sc;
        }
        *(float4*)&pt_out[grow + xs] = make_float4(bp[0], bp[1], bp[2], bp[3]);
    }
}

extern "C" void kernel_launch(void* const* d_in, const int* in_sizes, int n_in,
                              void* d_out, int out_size)
{
    const float* im = (const float*)d_in[0];
    const float* pt = (const float*)d_in[1];
    float* out = (float*)d_out;

    float *imA, *ptA, *imB, *ptB;
    cudaGetSymbolAddress((void**)&imA, g_imA);
    cudaGetSymbolAddress((void**)&ptA, g_ptA);
    cudaGetSymbolAddress((void**)&imB, g_imB);
    cudaGetSymbolAddress((void**)&ptB, g_ptB);

    dim3 grid(WW / TX, HH / TY, NIMG);   // (8,16,12) = 1536 blocks
    dim3 block(256);

    swf_step<<<grid, block>>>(im,  pt,  imA, ptA, 1);
    swf_step<<<grid, block>>>(imA, ptA, imB, ptB, 1);
    swf_step<<<grid, block>>>(imB, ptB, imA, ptA, 1);
    swf_step<<<grid, block>>>(imA, ptA, imB, ptB, 1);
    swf_step<<<grid, block>>>(imB, ptB, imA, ptA, 1);
    swf_step<<<grid, block>>>(imA, ptA, imB, out, 0);
}